// round 5
// baseline (speedup 1.0000x reference)
#include <cuda_runtime.h>
#include <cuda_fp16.h>
#include <math.h>
#include <stdint.h>

#define N 2048
#define NN (N * N)

// ---------------------------------------------------------------------------
// Scratch (__device__ globals; allocation-free rule)
// Each split tensor = 2 fp16 planes [hi, lo], layout [2][NN].
// A-form: [M,K] row-major of the matrix. B-form: [N,K] row-major (= M^T).
// ---------------------------------------------------------------------------
__device__ float  g_QK[NN];      // logits (fp32), softmax input
__device__ __half g_xS[2][NN];   // x      A-form
__device__ __half g_qS[2][NN];   // q^T    B-form
__device__ __half g_kS[2][NN];   // k^T    B-form
__device__ __half g_vS[2][NN];   // v^T    B-form
__device__ __half g_A1S[2][NN];  // (x@q)      A-form
__device__ __half g_B1S[2][NN];  // (x@k)^T    B-form
__device__ __half g_C1S[2][NN];  // (x@v)^T    B-form
__device__ __half g_atS[2][NN];  // softmax(QK) A-form

// ---------------------------------------------------------------------------
// PTX helpers (sm_80-era, legal on compute_103)
// ---------------------------------------------------------------------------
__device__ __forceinline__ uint32_t smem_to_u32(const void* p) {
    uint32_t a;
    asm("{ .reg .u64 t; cvta.to.shared.u64 t, %1; cvt.u32.u64 %0, t; }"
        : "=r"(a) : "l"(p));
    return a;
}
__device__ __forceinline__ void cp_async16(uint32_t saddr, const void* gaddr) {
    asm volatile("cp.async.cg.shared.global [%0], [%1], 16;"
                 :: "r"(saddr), "l"(gaddr) : "memory");
}
__device__ __forceinline__ void cp_commit() {
    asm volatile("cp.async.commit_group;" ::: "memory");
}
__device__ __forceinline__ void ldsm4(uint32_t* r, uint32_t addr) {
    asm volatile("ldmatrix.sync.aligned.m8n8.x4.shared.b16 {%0,%1,%2,%3}, [%4];"
                 : "=r"(r[0]), "=r"(r[1]), "=r"(r[2]), "=r"(r[3]) : "r"(addr));
}
__device__ __forceinline__ void mma16816(float* c, const uint32_t* a,
                                         uint32_t b0, uint32_t b1) {
    asm volatile(
        "mma.sync.aligned.m16n8k16.row.col.f32.f16.f16.f32 "
        "{%0,%1,%2,%3}, {%4,%5,%6,%7}, {%8,%9}, {%0,%1,%2,%3};"
        : "+f"(c[0]), "+f"(c[1]), "+f"(c[2]), "+f"(c[3])
        : "r"(a[0]), "r"(a[1]), "r"(a[2]), "r"(a[3]), "r"(b0), "r"(b1));
}

// ---------------------------------------------------------------------------
// GEMM: C[M,N] = Ah@Bh^T + Al@Bh^T + Ah@Bl^T   (fp16 planes, fp32 accum)
//   A: [2][M][K] planes (A-form), B: [2][N][K] planes (B-form)
// Tile 128x128, BK=32, 256 thr (2x4 warps, 64x32 warp tile),
// 2-stage cp.async pipeline, 2 CTAs/SM.
// If SPLIT: epilogue writes fp16 hi/lo planes of C; else fp32 C.
// ---------------------------------------------------------------------------
#define TILEB 10240                 // 128 rows * 80B (64B data + 16B pad)
#define STAGE (4 * TILEB)           // Ah, Al, Bh, Bl = 40960 B
#define SMEM_GEMM (2 * STAGE)       // 2 stages = 81920 B

template <bool SPLIT>
__global__ __launch_bounds__(256, 2) void gemm3_kernel(
    const __half* __restrict__ A,    // [2][NN]
    const __half* __restrict__ B,    // [2][NN]
    float* __restrict__ Cf,          // used if !SPLIT
    __half* __restrict__ Cp)         // [2][NN], used if SPLIT
{
    extern __shared__ char smem[];
    const uint32_t sbase = smem_to_u32(smem);
    const int tid  = threadIdx.x;
    const int lane = tid & 31;
    const int wid  = tid >> 5;
    const int wm   = wid >> 2;            // 0..1
    const int wn   = wid & 3;             // 0..3
    const int brow = blockIdx.y * 128;
    const int bcol = blockIdx.x * 128;

    float acc[4][4][4];
#pragma unroll
    for (int i = 0; i < 4; i++)
#pragma unroll
        for (int j = 0; j < 4; j++)
#pragma unroll
            for (int q = 0; q < 4; q++) acc[i][j][q] = 0.0f;

    // per-thread load coords: 512 16B-chunks per plane-tile -> 2/thread
    const int lrow0 = tid >> 2;           // 0..63
    const int lch   = tid & 3;            // 0..3

    auto load_stage = [&](int s, int k0) {
        const uint32_t st = sbase + s * STAGE;
#pragma unroll
        for (int p = 0; p < 2; p++) {
            const __half* src = A + (size_t)p * NN;
#pragma unroll
            for (int rep = 0; rep < 2; rep++) {
                const int row = lrow0 + rep * 64;
                cp_async16(st + p * TILEB + row * 80 + lch * 16,
                           src + (size_t)(brow + row) * N + k0 + lch * 8);
            }
        }
#pragma unroll
        for (int p = 0; p < 2; p++) {
            const __half* src = B + (size_t)p * NN;
#pragma unroll
            for (int rep = 0; rep < 2; rep++) {
                const int row = lrow0 + rep * 64;
                cp_async16(st + (2 + p) * TILEB + row * 80 + lch * 16,
                           src + (size_t)(bcol + row) * N + k0 + lch * 8);
            }
        }
        cp_commit();
    };

    auto compute_stage = [&](int s) {
        const uint32_t st = sbase + s * STAGE;
#pragma unroll
        for (int ks = 0; ks < 2; ks++) {
            // A fragments, both planes (hoisted; reused across terms)
            uint32_t a[2][4][4];
            const uint32_t arow  = wm * 64 + (lane & 15);
            const uint32_t acol2 = (ks * 16 + ((lane >> 4) << 3)) * 2;
#pragma unroll
            for (int p = 0; p < 2; p++)
#pragma unroll
                for (int mf = 0; mf < 4; mf++)
                    ldsm4(a[p][mf],
                          st + p * TILEB + (arow + mf * 16) * 80 + acol2);

            const uint32_t brw   = wn * 32 + (lane & 7) + ((lane >> 4) << 3);
            const uint32_t bcol2 = (ks * 16 + ((lane >> 3) & 1) * 8) * 2;

            // B hi plane -> terms (Ah,Bh), (Al,Bh)
            uint32_t b[2][4];
#pragma unroll
            for (int nh = 0; nh < 2; nh++)
                ldsm4(b[nh], st + 2 * TILEB + (brw + nh * 16) * 80 + bcol2);
#pragma unroll
            for (int pa = 0; pa < 2; pa++)
#pragma unroll
                for (int mf = 0; mf < 4; mf++)
#pragma unroll
                    for (int nf = 0; nf < 4; nf++)
                        mma16816(acc[mf][nf], a[pa][mf],
                                 b[nf >> 1][(nf & 1) * 2],
                                 b[nf >> 1][(nf & 1) * 2 + 1]);

            // B lo plane -> term (Ah,Bl)  (reuse b regs)
#pragma unroll
            for (int nh = 0; nh < 2; nh++)
                ldsm4(b[nh], st + 3 * TILEB + (brw + nh * 16) * 80 + bcol2);
#pragma unroll
            for (int mf = 0; mf < 4; mf++)
#pragma unroll
                for (int nf = 0; nf < 4; nf++)
                    mma16816(acc[mf][nf], a[0][mf],
                             b[nf >> 1][(nf & 1) * 2],
                             b[nf >> 1][(nf & 1) * 2 + 1]);
        }
    };

    // ---- 2-stage pipeline, K = 2048 -> 64 iters
    load_stage(0, 0);
    for (int it = 0; it < 64; it++) {
        if (it + 1 < 64) {
            load_stage((it + 1) & 1, (it + 1) * 32);
            asm volatile("cp.async.wait_group 1;" ::: "memory");
        } else {
            asm volatile("cp.async.wait_group 0;" ::: "memory");
        }
        __syncthreads();
        compute_stage(it & 1);
        __syncthreads();   // buffer (it&1) free before next iter's load
    }

    // ---- epilogue
    const int row0 = brow + wm * 64 + (lane >> 2);
    const int col0 = bcol + wn * 32 + (lane & 3) * 2;
#pragma unroll
    for (int mf = 0; mf < 4; mf++) {
#pragma unroll
        for (int nf = 0; nf < 4; nf++) {
#pragma unroll
            for (int half_id = 0; half_id < 2; half_id++) {
                const size_t off = (size_t)(row0 + mf * 16 + half_id * 8) * N
                                   + col0 + nf * 8;
                float c0 = acc[mf][nf][half_id * 2];
                float c1 = acc[mf][nf][half_id * 2 + 1];
                if (SPLIT) {
                    __half h0 = __float2half_rn(c0);
                    __half h1 = __float2half_rn(c1);
                    __half l0 = __float2half_rn(c0 - __half2float(h0));
                    __half l1 = __float2half_rn(c1 - __half2float(h1));
                    *(__half2*)&Cp[off]              = __halves2half2(h0, h1);
                    *(__half2*)&Cp[(size_t)NN + off] = __halves2half2(l0, l1);
                } else {
                    *(float2*)&Cf[off] = make_float2(c0, c1);
                }
            }
        }
    }
}

// ---------------------------------------------------------------------------
// Split fp32 -> 2 fp16 planes, same layout (A-form), 2 elems/thread
// ---------------------------------------------------------------------------
__global__ __launch_bounds__(256) void split_kernel(
    const float* __restrict__ in, __half* __restrict__ out)
{
    const size_t i = (size_t)blockIdx.x * blockDim.x + threadIdx.x;
    const float2 a = *(const float2*)(in + 2 * i);
    __half hx = __float2half_rn(a.x);
    __half hy = __float2half_rn(a.y);
    __half lx = __float2half_rn(a.x - __half2float(hx));
    __half ly = __float2half_rn(a.y - __half2float(hy));
    *(__half2*)(out + 2 * i)              = __halves2half2(hx, hy);
    *(__half2*)(out + (size_t)NN + 2 * i) = __halves2half2(lx, ly);
}

// ---------------------------------------------------------------------------
// Split + transpose: fp32 [K,N] -> 2 fp16 planes [N,K] (B-form)
// ---------------------------------------------------------------------------
__global__ __launch_bounds__(256) void split_transpose_kernel(
    const float* __restrict__ in, __half* __restrict__ out)
{
    __shared__ float t[32][33];
    const int tx = threadIdx.x;
    const int ty = threadIdx.y;
    const int k0 = blockIdx.y * 32;
    const int n0 = blockIdx.x * 32;

#pragma unroll
    for (int r = ty; r < 32; r += 8)
        t[r][tx] = in[(size_t)(k0 + r) * N + n0 + tx];
    __syncthreads();

#pragma unroll
    for (int r = ty; r < 32; r += 8) {
        float a = t[tx][r];
        __half h = __float2half_rn(a);
        __half l = __float2half_rn(a - __half2float(h));
        const size_t o = (size_t)(n0 + r) * N + k0 + tx;
        out[o]              = h;
        out[(size_t)NN + o] = l;
    }
}

// ---------------------------------------------------------------------------
// Row softmax (fp32 in) fused with fp16 split-out (A-form planes)
// ---------------------------------------------------------------------------
__global__ __launch_bounds__(256) void softmax_split_kernel(
    const float* __restrict__ M, __half* __restrict__ out)
{
    __shared__ float red[256];
    const int row = blockIdx.x;
    const int tid = threadIdx.x;
    const float* r = M + (size_t)row * N;

    float vals[8];
    float lmax = -INFINITY;
#pragma unroll
    for (int i = 0; i < 8; i++) {
        vals[i] = r[tid + i * 256];
        lmax = fmaxf(lmax, vals[i]);
    }
    red[tid] = lmax;
    __syncthreads();
#pragma unroll
    for (int s = 128; s > 0; s >>= 1) {
        if (tid < s) red[tid] = fmaxf(red[tid], red[tid + s]);
        __syncthreads();
    }
    const float m = red[0];
    __syncthreads();

    float lsum = 0.0f;
#pragma unroll
    for (int i = 0; i < 8; i++) {
        vals[i] = expf(vals[i] - m);
        lsum += vals[i];
    }
    red[tid] = lsum;
    __syncthreads();
#pragma unroll
    for (int s = 128; s > 0; s >>= 1) {
        if (tid < s) red[tid] += red[tid + s];
        __syncthreads();
    }
    const float inv = 1.0f / red[0];
#pragma unroll
    for (int i = 0; i < 8; i++) {
        float a = vals[i] * inv;
        __half h = __float2half_rn(a);
        __half l = __float2half_rn(a - __half2float(h));
        const size_t o = (size_t)row * N + tid + i * 256;
        out[o]              = h;
        out[(size_t)NN + o] = l;
    }
}

// ---------------------------------------------------------------------------
// kernel_launch  —  inputs (metadata order): x, q, k, v  (float32 [N*N])
// ---------------------------------------------------------------------------
extern "C" void kernel_launch(void* const* d_in, const int* in_sizes, int n_in,
                              void* d_out, int out_size)
{
    const float* x = (const float*)d_in[0];
    const float* q = (const float*)d_in[1];
    const float* k = (const float*)d_in[2];
    const float* v = (const float*)d_in[3];
    float* out = (float*)d_out;

    float* pQK;
    cudaGetSymbolAddress((void**)&pQK, g_QK);
    __half *pxS, *pqS, *pkS, *pvS, *pA1S, *pB1S, *pC1S, *patS;
    cudaGetSymbolAddress((void**)&pxS,  g_xS);
    cudaGetSymbolAddress((void**)&pqS,  g_qS);
    cudaGetSymbolAddress((void**)&pkS,  g_kS);
    cudaGetSymbolAddress((void**)&pvS,  g_vS);
    cudaGetSymbolAddress((void**)&pA1S, g_A1S);
    cudaGetSymbolAddress((void**)&pB1S, g_B1S);
    cudaGetSymbolAddress((void**)&pC1S, g_C1S);
    cudaGetSymbolAddress((void**)&patS, g_atS);

    cudaFuncSetAttribute(gemm3_kernel<true>,
                         cudaFuncAttributeMaxDynamicSharedMemorySize, SMEM_GEMM);
    cudaFuncSetAttribute(gemm3_kernel<false>,
                         cudaFuncAttributeMaxDynamicSharedMemorySize, SMEM_GEMM);

    const dim3 gGemm(N / 128, N / 128);
    const dim3 gSplit(NN / 512);
    const dim3 gTr(N / 32, N / 32);
    const dim3 bTr(32, 8);

    // input splits
    split_kernel<<<gSplit, 256>>>(x, pxS);                 // x   -> A-form
    split_transpose_kernel<<<gTr, bTr>>>(q, pqS);          // q^T -> B-form
    split_transpose_kernel<<<gTr, bTr>>>(k, pkS);          // k^T -> B-form
    split_transpose_kernel<<<gTr, bTr>>>(v, pvS);          // v^T -> B-form

    // layer 1 (split fused into epilogue; transposed products avoid transposes)
    gemm3_kernel<true><<<gGemm, 256, SMEM_GEMM>>>(pxS, pqS, nullptr, pA1S); // x@q   (A-form)
    gemm3_kernel<true><<<gGemm, 256, SMEM_GEMM>>>(pkS, pxS, nullptr, pB1S); // (x@k)^T (B-form)
    gemm3_kernel<true><<<gGemm, 256, SMEM_GEMM>>>(pvS, pxS, nullptr, pC1S); // (x@v)^T (B-form)

    // logits + softmax
    gemm3_kernel<false><<<gGemm, 256, SMEM_GEMM>>>(pA1S, pB1S, pQK, nullptr);
    softmax_split_kernel<<<N, 256>>>(pQK, patS);

    // output
    gemm3_kernel<false><<<gGemm, 256, SMEM_GEMM>>>(patS, pC1S, out, nullptr);
}

// round 6
// speedup vs baseline: 1.0856x; 1.0856x over previous
#include <cuda_runtime.h>
#include <cuda_fp16.h>
#include <math.h>
#include <stdint.h>

#define N 2048
#define NN (N * N)

// ---------------------------------------------------------------------------
// Scratch (__device__ globals; allocation-free rule)
// Each split tensor = 2 fp16 planes [hi, lo], layout [2][NN].
// A-form: [M,K] row-major of the matrix. B-form: [N,K] row-major (= M^T).
// ---------------------------------------------------------------------------
__device__ float  g_QK[NN];      // logits (fp32), softmax input
__device__ __half g_xS[2][NN];   // x      A-form
__device__ __half g_qS[2][NN];   // q^T    B-form
__device__ __half g_kS[2][NN];   // k^T    B-form
__device__ __half g_vS[2][NN];   // v^T    B-form
__device__ __half g_A1S[2][NN];  // (x@q)      A-form
__device__ __half g_B1S[2][NN];  // (x@k)^T    B-form
__device__ __half g_C1S[2][NN];  // (x@v)^T    B-form
__device__ __half g_atS[2][NN];  // softmax(QK) A-form

// ---------------------------------------------------------------------------
// PTX helpers (sm_80-era, legal on compute_103)
// ---------------------------------------------------------------------------
__device__ __forceinline__ uint32_t smem_to_u32(const void* p) {
    uint32_t a;
    asm("{ .reg .u64 t; cvta.to.shared.u64 t, %1; cvt.u32.u64 %0, t; }"
        : "=r"(a) : "l"(p));
    return a;
}
__device__ __forceinline__ void cp_async16(uint32_t saddr, const void* gaddr) {
    asm volatile("cp.async.cg.shared.global [%0], [%1], 16;"
                 :: "r"(saddr), "l"(gaddr) : "memory");
}
__device__ __forceinline__ void cp_commit() {
    asm volatile("cp.async.commit_group;" ::: "memory");
}
__device__ __forceinline__ void ldsm4(uint32_t* r, uint32_t addr) {
    asm volatile("ldmatrix.sync.aligned.m8n8.x4.shared.b16 {%0,%1,%2,%3}, [%4];"
                 : "=r"(r[0]), "=r"(r[1]), "=r"(r[2]), "=r"(r[3]) : "r"(addr));
}
__device__ __forceinline__ void mma16816(float* c, const uint32_t* a,
                                         uint32_t b0, uint32_t b1) {
    asm volatile(
        "mma.sync.aligned.m16n8k16.row.col.f32.f16.f16.f32 "
        "{%0,%1,%2,%3}, {%4,%5,%6,%7}, {%8,%9}, {%0,%1,%2,%3};"
        : "+f"(c[0]), "+f"(c[1]), "+f"(c[2]), "+f"(c[3])
        : "r"(a[0]), "r"(a[1]), "r"(a[2]), "r"(a[3]), "r"(b0), "r"(b1));
}

// ---------------------------------------------------------------------------
// GEMM: C[M,N] = Ah@Bh^T + Al@Bh^T + Ah@Bl^T   (fp16 planes, fp32 accum)
//   A: [2][M][K] planes (A-form), B: [2][N][K] planes (B-form)
// Tile 128x256, BK=32, 256 thr (2x4 warps, 64x64 warp tile), 3-stage cp.async.
// If SPLIT: epilogue writes fp16 hi/lo planes of C; else fp32 C.
// ---------------------------------------------------------------------------
#define TA 10240                    // A plane-tile: 128 rows * 80B
#define TB 20480                    // B plane-tile: 256 rows * 80B
#define STAGE (2 * TA + 2 * TB)     // Ah, Al, Bh, Bl = 61440 B
#define SMEM_GEMM (3 * STAGE)       // 3 stages = 184320 B

template <bool SPLIT>
__global__ __launch_bounds__(256, 1) void gemm3_kernel(
    const __half* __restrict__ A,    // [2][NN]
    const __half* __restrict__ B,    // [2][NN]
    float* __restrict__ Cf,          // used if !SPLIT
    __half* __restrict__ Cp)         // [2][NN], used if SPLIT
{
    extern __shared__ char smem[];
    const uint32_t sbase = smem_to_u32(smem);
    const int tid  = threadIdx.x;
    const int lane = tid & 31;
    const int wid  = tid >> 5;
    const int wm   = wid >> 2;            // 0..1  (64-row slice)
    const int wn   = wid & 3;             // 0..3  (64-col slice)
    const int brow = blockIdx.y * 128;
    const int bcol = blockIdx.x * 256;

    float acc[4][8][4];
#pragma unroll
    for (int i = 0; i < 4; i++)
#pragma unroll
        for (int j = 0; j < 8; j++)
#pragma unroll
            for (int q = 0; q < 4; q++) acc[i][j][q] = 0.0f;

    // loaders: chunks of 16B; A plane = 512 chunks (2/thread), B plane = 1024 (4/thread)
    const int lrow = tid >> 2;            // 0..63
    const int lch  = tid & 3;             // 0..3

    auto load_stage = [&](int s, int k0) {
        const uint32_t st = sbase + s * STAGE;
#pragma unroll
        for (int p = 0; p < 2; p++) {
            const __half* src = A + (size_t)p * NN;
#pragma unroll
            for (int rep = 0; rep < 2; rep++) {
                const int row = lrow + rep * 64;
                cp_async16(st + p * TA + row * 80 + lch * 16,
                           src + (size_t)(brow + row) * N + k0 + lch * 8);
            }
        }
#pragma unroll
        for (int p = 0; p < 2; p++) {
            const __half* src = B + (size_t)p * NN;
#pragma unroll
            for (int rep = 0; rep < 4; rep++) {
                const int row = lrow + rep * 64;
                cp_async16(st + 2 * TA + p * TB + row * 80 + lch * 16,
                           src + (size_t)(bcol + row) * N + k0 + lch * 8);
            }
        }
        cp_commit();
    };

    auto compute_stage = [&](int s) {
        const uint32_t st = sbase + s * STAGE;
#pragma unroll
        for (int ks = 0; ks < 2; ks++) {
            // A fragments, both planes (reused across all 8 nf)
            uint32_t a[2][4][4];
            const uint32_t arow  = wm * 64 + (lane & 15);
            const uint32_t acol2 = (ks * 16 + ((lane >> 4) << 3)) * 2;
#pragma unroll
            for (int p = 0; p < 2; p++)
#pragma unroll
                for (int mf = 0; mf < 4; mf++)
                    ldsm4(a[p][mf],
                          st + p * TA + (arow + mf * 16) * 80 + acol2);

            const uint32_t brw   = wn * 64 + (lane & 7) + ((lane >> 4) << 3);
            const uint32_t bcol2 = (ks * 16 + ((lane >> 3) & 1) * 8) * 2;

            // B hi plane -> terms (Ah,Bh), (Al,Bh)
            uint32_t b[4][4];
#pragma unroll
            for (int nh = 0; nh < 4; nh++)
                ldsm4(b[nh], st + 2 * TA + (brw + nh * 16) * 80 + bcol2);
#pragma unroll
            for (int pa = 0; pa < 2; pa++)
#pragma unroll
                for (int mf = 0; mf < 4; mf++)
#pragma unroll
                    for (int nf = 0; nf < 8; nf++)
                        mma16816(acc[mf][nf], a[pa][mf],
                                 b[nf >> 1][(nf & 1) * 2],
                                 b[nf >> 1][(nf & 1) * 2 + 1]);

            // B lo plane -> term (Ah,Bl)  (reuse b regs)
#pragma unroll
            for (int nh = 0; nh < 4; nh++)
                ldsm4(b[nh], st + 2 * TA + TB + (brw + nh * 16) * 80 + bcol2);
#pragma unroll
            for (int mf = 0; mf < 4; mf++)
#pragma unroll
                for (int nf = 0; nf < 8; nf++)
                    mma16816(acc[mf][nf], a[0][mf],
                             b[nf >> 1][(nf & 1) * 2],
                             b[nf >> 1][(nf & 1) * 2 + 1]);
        }
    };

    // ---- 3-stage pipeline, K = 2048 -> 64 iters
    load_stage(0, 0);
    load_stage(1, 32);
    for (int it = 0; it < 64; it++) {
        if (it < 63) {
            asm volatile("cp.async.wait_group 1;" ::: "memory");
        } else {
            asm volatile("cp.async.wait_group 0;" ::: "memory");
        }
        __syncthreads();
        compute_stage(it % 3);
        if (it + 2 < 64) load_stage((it + 2) % 3, (it + 2) * 32);
    }

    // ---- epilogue
    const int row0 = brow + wm * 64 + (lane >> 2);
    const int col0 = bcol + wn * 64 + (lane & 3) * 2;
#pragma unroll
    for (int mf = 0; mf < 4; mf++) {
#pragma unroll
        for (int nf = 0; nf < 8; nf++) {
#pragma unroll
            for (int half_id = 0; half_id < 2; half_id++) {
                const size_t off = (size_t)(row0 + mf * 16 + half_id * 8) * N
                                   + col0 + nf * 8;
                float c0 = acc[mf][nf][half_id * 2];
                float c1 = acc[mf][nf][half_id * 2 + 1];
                if (SPLIT) {
                    __half h0 = __float2half_rn(c0);
                    __half h1 = __float2half_rn(c1);
                    __half l0 = __float2half_rn(c0 - __half2float(h0));
                    __half l1 = __float2half_rn(c1 - __half2float(h1));
                    *(__half2*)&Cp[off]              = __halves2half2(h0, h1);
                    *(__half2*)&Cp[(size_t)NN + off] = __halves2half2(l0, l1);
                } else {
                    *(float2*)&Cf[off] = make_float2(c0, c1);
                }
            }
        }
    }
}

// ---------------------------------------------------------------------------
// Split fp32 -> 2 fp16 planes, same layout (A-form), 2 elems/thread
// ---------------------------------------------------------------------------
__global__ __launch_bounds__(256) void split_kernel(
    const float* __restrict__ in, __half* __restrict__ out)
{
    const size_t i = (size_t)blockIdx.x * blockDim.x + threadIdx.x;
    const float2 a = *(const float2*)(in + 2 * i);
    __half hx = __float2half_rn(a.x);
    __half hy = __float2half_rn(a.y);
    __half lx = __float2half_rn(a.x - __half2float(hx));
    __half ly = __float2half_rn(a.y - __half2float(hy));
    *(__half2*)(out + 2 * i)              = __halves2half2(hx, hy);
    *(__half2*)(out + (size_t)NN + 2 * i) = __halves2half2(lx, ly);
}

// ---------------------------------------------------------------------------
// Split + transpose: fp32 [K,N] -> 2 fp16 planes [N,K] (B-form)
// ---------------------------------------------------------------------------
__global__ __launch_bounds__(256) void split_transpose_kernel(
    const float* __restrict__ in, __half* __restrict__ out)
{
    __shared__ float t[32][33];
    const int tx = threadIdx.x;
    const int ty = threadIdx.y;
    const int k0 = blockIdx.y * 32;
    const int n0 = blockIdx.x * 32;

#pragma unroll
    for (int r = ty; r < 32; r += 8)
        t[r][tx] = in[(size_t)(k0 + r) * N + n0 + tx];
    __syncthreads();

#pragma unroll
    for (int r = ty; r < 32; r += 8) {
        float a = t[tx][r];
        __half h = __float2half_rn(a);
        __half l = __float2half_rn(a - __half2float(h));
        const size_t o = (size_t)(n0 + r) * N + k0 + tx;
        out[o]              = h;
        out[(size_t)NN + o] = l;
    }
}

// ---------------------------------------------------------------------------
// Row softmax (fp32 in) fused with fp16 split-out (A-form planes)
// ---------------------------------------------------------------------------
__global__ __launch_bounds__(256) void softmax_split_kernel(
    const float* __restrict__ M, __half* __restrict__ out)
{
    __shared__ float red[256];
    const int row = blockIdx.x;
    const int tid = threadIdx.x;
    const float* r = M + (size_t)row * N;

    float vals[8];
    float lmax = -INFINITY;
#pragma unroll
    for (int i = 0; i < 8; i++) {
        vals[i] = r[tid + i * 256];
        lmax = fmaxf(lmax, vals[i]);
    }
    red[tid] = lmax;
    __syncthreads();
#pragma unroll
    for (int s = 128; s > 0; s >>= 1) {
        if (tid < s) red[tid] = fmaxf(red[tid], red[tid + s]);
        __syncthreads();
    }
    const float m = red[0];
    __syncthreads();

    float lsum = 0.0f;
#pragma unroll
    for (int i = 0; i < 8; i++) {
        vals[i] = expf(vals[i] - m);
        lsum += vals[i];
    }
    red[tid] = lsum;
    __syncthreads();
#pragma unroll
    for (int s = 128; s > 0; s >>= 1) {
        if (tid < s) red[tid] += red[tid + s];
        __syncthreads();
    }
    const float inv = 1.0f / red[0];
#pragma unroll
    for (int i = 0; i < 8; i++) {
        float a = vals[i] * inv;
        __half h = __float2half_rn(a);
        __half l = __float2half_rn(a - __half2float(h));
        const size_t o = (size_t)row * N + tid + i * 256;
        out[o]              = h;
        out[(size_t)NN + o] = l;
    }
}

// ---------------------------------------------------------------------------
// kernel_launch  —  inputs (metadata order): x, q, k, v  (float32 [N*N])
// ---------------------------------------------------------------------------
extern "C" void kernel_launch(void* const* d_in, const int* in_sizes, int n_in,
                              void* d_out, int out_size)
{
    const float* x = (const float*)d_in[0];
    const float* q = (const float*)d_in[1];
    const float* k = (const float*)d_in[2];
    const float* v = (const float*)d_in[3];
    float* out = (float*)d_out;

    float* pQK;
    cudaGetSymbolAddress((void**)&pQK, g_QK);
    __half *pxS, *pqS, *pkS, *pvS, *pA1S, *pB1S, *pC1S, *patS;
    cudaGetSymbolAddress((void**)&pxS,  g_xS);
    cudaGetSymbolAddress((void**)&pqS,  g_qS);
    cudaGetSymbolAddress((void**)&pkS,  g_kS);
    cudaGetSymbolAddress((void**)&pvS,  g_vS);
    cudaGetSymbolAddress((void**)&pA1S, g_A1S);
    cudaGetSymbolAddress((void**)&pB1S, g_B1S);
    cudaGetSymbolAddress((void**)&pC1S, g_C1S);
    cudaGetSymbolAddress((void**)&patS, g_atS);

    cudaFuncSetAttribute(gemm3_kernel<true>,
                         cudaFuncAttributeMaxDynamicSharedMemorySize, SMEM_GEMM);
    cudaFuncSetAttribute(gemm3_kernel<false>,
                         cudaFuncAttributeMaxDynamicSharedMemorySize, SMEM_GEMM);

    const dim3 gGemm(N / 256, N / 128);   // 8 x 16 = 128 CTAs (single wave)
    const dim3 gSplit(NN / 512);
    const dim3 gTr(N / 32, N / 32);
    const dim3 bTr(32, 8);

    // input splits
    split_kernel<<<gSplit, 256>>>(x, pxS);                 // x   -> A-form
    split_transpose_kernel<<<gTr, bTr>>>(q, pqS);          // q^T -> B-form
    split_transpose_kernel<<<gTr, bTr>>>(k, pkS);          // k^T -> B-form
    split_transpose_kernel<<<gTr, bTr>>>(v, pvS);          // v^T -> B-form

    // layer 1 (split fused into epilogue; transposed products avoid transposes)
    gemm3_kernel<true><<<gGemm, 256, SMEM_GEMM>>>(pxS, pqS, nullptr, pA1S); // x@q   (A-form)
    gemm3_kernel<true><<<gGemm, 256, SMEM_GEMM>>>(pkS, pxS, nullptr, pB1S); // (x@k)^T (B-form)
    gemm3_kernel<true><<<gGemm, 256, SMEM_GEMM>>>(pvS, pxS, nullptr, pC1S); // (x@v)^T (B-form)

    // logits + softmax
    gemm3_kernel<false><<<gGemm, 256, SMEM_GEMM>>>(pA1S, pB1S, pQK, nullptr);
    softmax_split_kernel<<<N, 256>>>(pQK, patS);

    // output
    gemm3_kernel<false><<<gGemm, 256, SMEM_GEMM>>>(patS, pC1S, out, nullptr);
}

// round 7
// speedup vs baseline: 1.3544x; 1.2476x over previous
#include <cuda_runtime.h>
#include <cuda_fp16.h>
#include <math.h>
#include <stdint.h>

#define N 2048
#define NN (N * N)

// ---------------------------------------------------------------------------
// Scratch (__device__ globals; allocation-free rule)
// Each split tensor = 2 fp16 planes [hi, lo], layout [2][NN].
// A-form: [M,K] row-major of the matrix. B-form: [N,K] row-major (= M^T).
// ---------------------------------------------------------------------------
__device__ float  g_QK[NN];      // logits (fp32)
__device__ float  g_C1[NN];      // x @ v (fp32, row-major)
__device__ __half g_xS[2][NN];   // x      A-form
__device__ __half g_qS[2][NN];   // q^T    B-form
__device__ __half g_kS[2][NN];   // k^T    B-form
__device__ __half g_vS[2][NN];   // v^T    B-form
__device__ __half g_A1S[2][NN];  // (x@q)      A-form
__device__ __half g_B1S[2][NN];  // (x@k)^T    B-form

// ---------------------------------------------------------------------------
// PTX helpers (sm_80-era, legal on compute_103)
// ---------------------------------------------------------------------------
__device__ __forceinline__ uint32_t smem_to_u32(const void* p) {
    uint32_t a;
    asm("{ .reg .u64 t; cvta.to.shared.u64 t, %1; cvt.u32.u64 %0, t; }"
        : "=r"(a) : "l"(p));
    return a;
}
__device__ __forceinline__ void cp_async16(uint32_t saddr, const void* gaddr) {
    asm volatile("cp.async.cg.shared.global [%0], [%1], 16;"
                 :: "r"(saddr), "l"(gaddr) : "memory");
}
__device__ __forceinline__ void cp_commit() {
    asm volatile("cp.async.commit_group;" ::: "memory");
}
__device__ __forceinline__ void ldsm4(uint32_t* r, uint32_t addr) {
    asm volatile("ldmatrix.sync.aligned.m8n8.x4.shared.b16 {%0,%1,%2,%3}, [%4];"
                 : "=r"(r[0]), "=r"(r[1]), "=r"(r[2]), "=r"(r[3]) : "r"(addr));
}
__device__ __forceinline__ void mma16816(float* c, const uint32_t* a,
                                         uint32_t b0, uint32_t b1) {
    asm volatile(
        "mma.sync.aligned.m16n8k16.row.col.f32.f16.f16.f32 "
        "{%0,%1,%2,%3}, {%4,%5,%6,%7}, {%8,%9}, {%0,%1,%2,%3};"
        : "+f"(c[0]), "+f"(c[1]), "+f"(c[2]), "+f"(c[3])
        : "r"(a[0]), "r"(a[1]), "r"(a[2]), "r"(a[3]), "r"(b0), "r"(b1));
}

// ---------------------------------------------------------------------------
// GEMM: C[M,N] = Ah@Bh^T + Al@Bh^T + Ah@Bl^T   (fp16 planes, fp32 accum)
// Tile 128x256, BK=32, 256 thr (2x4 warps, 64x64 warp tile), 3-stage cp.async.
// If SPLIT: epilogue writes fp16 hi/lo planes of C; else fp32 C.
// ---------------------------------------------------------------------------
#define TA 10240                    // A plane-tile: 128 rows * 80B
#define TB 20480                    // B plane-tile: 256 rows * 80B
#define STAGE (2 * TA + 2 * TB)     // Ah, Al, Bh, Bl = 61440 B
#define SMEM_GEMM (3 * STAGE)       // 3 stages = 184320 B

template <bool SPLIT>
__global__ __launch_bounds__(256, 1) void gemm3_kernel(
    const __half* __restrict__ A,    // [2][NN]
    const __half* __restrict__ B,    // [2][NN]
    float* __restrict__ Cf,          // used if !SPLIT
    __half* __restrict__ Cp)         // [2][NN], used if SPLIT
{
    extern __shared__ char smem[];
    const uint32_t sbase = smem_to_u32(smem);
    const int tid  = threadIdx.x;
    const int lane = tid & 31;
    const int wid  = tid >> 5;
    const int wm   = wid >> 2;            // 0..1  (64-row slice)
    const int wn   = wid & 3;             // 0..3  (64-col slice)
    const int brow = blockIdx.y * 128;
    const int bcol = blockIdx.x * 256;

    float acc[4][8][4];
#pragma unroll
    for (int i = 0; i < 4; i++)
#pragma unroll
        for (int j = 0; j < 8; j++)
#pragma unroll
            for (int q = 0; q < 4; q++) acc[i][j][q] = 0.0f;

    const int lrow = tid >> 2;            // 0..63
    const int lch  = tid & 3;             // 0..3

    auto load_stage = [&](int s, int k0) {
        const uint32_t st = sbase + s * STAGE;
#pragma unroll
        for (int p = 0; p < 2; p++) {
            const __half* src = A + (size_t)p * NN;
#pragma unroll
            for (int rep = 0; rep < 2; rep++) {
                const int row = lrow + rep * 64;
                cp_async16(st + p * TA + row * 80 + lch * 16,
                           src + (size_t)(brow + row) * N + k0 + lch * 8);
            }
        }
#pragma unroll
        for (int p = 0; p < 2; p++) {
            const __half* src = B + (size_t)p * NN;
#pragma unroll
            for (int rep = 0; rep < 4; rep++) {
                const int row = lrow + rep * 64;
                cp_async16(st + 2 * TA + p * TB + row * 80 + lch * 16,
                           src + (size_t)(bcol + row) * N + k0 + lch * 8);
            }
        }
        cp_commit();
    };

    auto compute_stage = [&](int s) {
        const uint32_t st = sbase + s * STAGE;
#pragma unroll
        for (int ks = 0; ks < 2; ks++) {
            uint32_t a[2][4][4];
            const uint32_t arow  = wm * 64 + (lane & 15);
            const uint32_t acol2 = (ks * 16 + ((lane >> 4) << 3)) * 2;
#pragma unroll
            for (int p = 0; p < 2; p++)
#pragma unroll
                for (int mf = 0; mf < 4; mf++)
                    ldsm4(a[p][mf],
                          st + p * TA + (arow + mf * 16) * 80 + acol2);

            const uint32_t brw   = wn * 64 + (lane & 7) + ((lane >> 4) << 3);
            const uint32_t bcol2 = (ks * 16 + ((lane >> 3) & 1) * 8) * 2;

            uint32_t b[4][4];
#pragma unroll
            for (int nh = 0; nh < 4; nh++)
                ldsm4(b[nh], st + 2 * TA + (brw + nh * 16) * 80 + bcol2);
#pragma unroll
            for (int pa = 0; pa < 2; pa++)
#pragma unroll
                for (int mf = 0; mf < 4; mf++)
#pragma unroll
                    for (int nf = 0; nf < 8; nf++)
                        mma16816(acc[mf][nf], a[pa][mf],
                                 b[nf >> 1][(nf & 1) * 2],
                                 b[nf >> 1][(nf & 1) * 2 + 1]);

#pragma unroll
            for (int nh = 0; nh < 4; nh++)
                ldsm4(b[nh], st + 2 * TA + TB + (brw + nh * 16) * 80 + bcol2);
#pragma unroll
            for (int mf = 0; mf < 4; mf++)
#pragma unroll
                for (int nf = 0; nf < 8; nf++)
                    mma16816(acc[mf][nf], a[0][mf],
                             b[nf >> 1][(nf & 1) * 2],
                             b[nf >> 1][(nf & 1) * 2 + 1]);
        }
    };

    load_stage(0, 0);
    load_stage(1, 32);
    for (int it = 0; it < 64; it++) {
        if (it < 63) {
            asm volatile("cp.async.wait_group 1;" ::: "memory");
        } else {
            asm volatile("cp.async.wait_group 0;" ::: "memory");
        }
        __syncthreads();
        compute_stage(it % 3);
        if (it + 2 < 64) load_stage((it + 2) % 3, (it + 2) * 32);
    }

    // ---- epilogue
    const int row0 = brow + wm * 64 + (lane >> 2);
    const int col0 = bcol + wn * 64 + (lane & 3) * 2;
#pragma unroll
    for (int mf = 0; mf < 4; mf++) {
#pragma unroll
        for (int nf = 0; nf < 8; nf++) {
#pragma unroll
            for (int half_id = 0; half_id < 2; half_id++) {
                const size_t off = (size_t)(row0 + mf * 16 + half_id * 8) * N
                                   + col0 + nf * 8;
                float c0 = acc[mf][nf][half_id * 2];
                float c1 = acc[mf][nf][half_id * 2 + 1];
                if (SPLIT) {
                    __half h0 = __float2half_rn(c0);
                    __half h1 = __float2half_rn(c1);
                    __half l0 = __float2half_rn(c0 - __half2float(h0));
                    __half l1 = __float2half_rn(c1 - __half2float(h1));
                    *(__half2*)&Cp[off]              = __halves2half2(h0, h1);
                    *(__half2*)&Cp[(size_t)NN + off] = __halves2half2(l0, l1);
                } else {
                    *(float2*)&Cf[off] = make_float2(c0, c1);
                }
            }
        }
    }
}

// ---------------------------------------------------------------------------
// Split fp32 -> 2 fp16 planes, same layout (A-form)
// ---------------------------------------------------------------------------
__global__ __launch_bounds__(256) void split_kernel(
    const float* __restrict__ in, __half* __restrict__ out)
{
    const size_t i = (size_t)blockIdx.x * blockDim.x + threadIdx.x;
    const float2 a = *(const float2*)(in + 2 * i);
    __half hx = __float2half_rn(a.x);
    __half hy = __float2half_rn(a.y);
    __half lx = __float2half_rn(a.x - __half2float(hx));
    __half ly = __float2half_rn(a.y - __half2float(hy));
    *(__half2*)(out + 2 * i)              = __halves2half2(hx, hy);
    *(__half2*)(out + (size_t)NN + 2 * i) = __halves2half2(lx, ly);
}

// ---------------------------------------------------------------------------
// Split + transpose: fp32 [K,N] -> 2 fp16 planes [N,K] (B-form)
// ---------------------------------------------------------------------------
__global__ __launch_bounds__(256) void split_transpose_kernel(
    const float* __restrict__ in, __half* __restrict__ out)
{
    __shared__ float t[32][33];
    const int tx = threadIdx.x;
    const int ty = threadIdx.y;
    const int k0 = blockIdx.y * 32;
    const int n0 = blockIdx.x * 32;

#pragma unroll
    for (int r = ty; r < 32; r += 8)
        t[r][tx] = in[(size_t)(k0 + r) * N + n0 + tx];
    __syncthreads();

#pragma unroll
    for (int r = ty; r < 32; r += 8) {
        float a = t[tx][r];
        __half h = __float2half_rn(a);
        __half l = __float2half_rn(a - __half2float(h));
        const size_t o = (size_t)(n0 + r) * N + k0 + tx;
        out[o]              = h;
        out[(size_t)NN + o] = l;
    }
}

// ---------------------------------------------------------------------------
// Fused softmax + sparse apply:
//   out[i,:] = sum_j w_ij * C1[j,:],  w = fp32 softmax of QK row i.
// Almost all w_ij are exactly 0 in fp32 (huge logit gaps) -> gather the
// few nonzero j in ascending order (deterministic).
// ---------------------------------------------------------------------------
__global__ __launch_bounds__(256) void softmax_apply_kernel(
    const float* __restrict__ QK, const float* __restrict__ C1,
    float* __restrict__ out)
{
    __shared__ float red[256];
    __shared__ float wrow[N];          // 8 KB: full attn row
    __shared__ uint32_t mask[N / 32];  // 256 B: nonzero bitmap

    const int row = blockIdx.x;
    const int tid = threadIdx.x;
    const float* r = QK + (size_t)row * N;

    float vals[8];
    float lmax = -INFINITY;
#pragma unroll
    for (int i = 0; i < 8; i++) {
        vals[i] = r[tid + i * 256];
        lmax = fmaxf(lmax, vals[i]);
    }
    red[tid] = lmax;
    if (tid < N / 32) mask[tid] = 0;
    __syncthreads();
#pragma unroll
    for (int s = 128; s > 0; s >>= 1) {
        if (tid < s) red[tid] = fmaxf(red[tid], red[tid + s]);
        __syncthreads();
    }
    const float m = red[0];
    __syncthreads();

    float lsum = 0.0f;
#pragma unroll
    for (int i = 0; i < 8; i++) {
        vals[i] = expf(vals[i] - m);
        lsum += vals[i];
    }
    red[tid] = lsum;
    __syncthreads();
#pragma unroll
    for (int s = 128; s > 0; s >>= 1) {
        if (tid < s) red[tid] += red[tid + s];
        __syncthreads();
    }
    const float inv = 1.0f / red[0];
    __syncthreads();

    // weights + nonzero bitmap
#pragma unroll
    for (int i = 0; i < 8; i++) {
        const int e = tid + i * 256;
        const float w = vals[i] * inv;
        wrow[e] = w;
        if (w != 0.0f) atomicOr(&mask[e >> 5], 1u << (e & 31));
    }
    __syncthreads();

    // ordered sparse gather: col c owned by this thread = tid + 256*cc
    float acc[8];
#pragma unroll
    for (int c = 0; c < 8; c++) acc[c] = 0.0f;

    for (int wrd = 0; wrd < N / 32; wrd++) {
        uint32_t mw = mask[wrd];
        while (mw) {
            const int b = __ffs(mw) - 1;
            mw &= mw - 1;
            const int e = wrd * 32 + b;
            const float w = wrow[e];
            const float* crow = C1 + (size_t)e * N;
#pragma unroll
            for (int c = 0; c < 8; c++)
                acc[c] = fmaf(w, crow[tid + c * 256], acc[c]);
        }
    }

    float* o = out + (size_t)row * N;
#pragma unroll
    for (int c = 0; c < 8; c++) o[tid + c * 256] = acc[c];
}

// ---------------------------------------------------------------------------
// kernel_launch  —  inputs (metadata order): x, q, k, v  (float32 [N*N])
// ---------------------------------------------------------------------------
extern "C" void kernel_launch(void* const* d_in, const int* in_sizes, int n_in,
                              void* d_out, int out_size)
{
    const float* x = (const float*)d_in[0];
    const float* q = (const float*)d_in[1];
    const float* k = (const float*)d_in[2];
    const float* v = (const float*)d_in[3];
    float* out = (float*)d_out;

    float *pQK, *pC1;
    cudaGetSymbolAddress((void**)&pQK, g_QK);
    cudaGetSymbolAddress((void**)&pC1, g_C1);
    __half *pxS, *pqS, *pkS, *pvS, *pA1S, *pB1S;
    cudaGetSymbolAddress((void**)&pxS,  g_xS);
    cudaGetSymbolAddress((void**)&pqS,  g_qS);
    cudaGetSymbolAddress((void**)&pkS,  g_kS);
    cudaGetSymbolAddress((void**)&pvS,  g_vS);
    cudaGetSymbolAddress((void**)&pA1S, g_A1S);
    cudaGetSymbolAddress((void**)&pB1S, g_B1S);

    cudaFuncSetAttribute(gemm3_kernel<true>,
                         cudaFuncAttributeMaxDynamicSharedMemorySize, SMEM_GEMM);
    cudaFuncSetAttribute(gemm3_kernel<false>,
                         cudaFuncAttributeMaxDynamicSharedMemorySize, SMEM_GEMM);

    const dim3 gGemm(N / 256, N / 128);   // 8 x 16 = 128 CTAs (single wave)
    const dim3 gSplit(NN / 512);
    const dim3 gTr(N / 32, N / 32);
    const dim3 bTr(32, 8);

    // input splits
    split_kernel<<<gSplit, 256>>>(x, pxS);                 // x   -> A-form
    split_transpose_kernel<<<gTr, bTr>>>(q, pqS);          // q^T -> B-form
    split_transpose_kernel<<<gTr, bTr>>>(k, pkS);          // k^T -> B-form
    split_transpose_kernel<<<gTr, bTr>>>(v, pvS);          // v^T -> B-form

    // layer 1
    gemm3_kernel<true><<<gGemm, 256, SMEM_GEMM>>>(pxS, pqS, nullptr, pA1S);  // x@q  (A-form planes)
    gemm3_kernel<true><<<gGemm, 256, SMEM_GEMM>>>(pkS, pxS, nullptr, pB1S);  // (x@k)^T (B-form planes)
    gemm3_kernel<false><<<gGemm, 256, SMEM_GEMM>>>(pxS, pvS, pC1, nullptr);  // x@v  (fp32 row-major)

    // logits
    gemm3_kernel<false><<<gGemm, 256, SMEM_GEMM>>>(pA1S, pB1S, pQK, nullptr);

    // fused softmax + sparse apply
    softmax_apply_kernel<<<N, 256>>>(pQK, pC1, out);
}